// round 10
// baseline (speedup 1.0000x reference)
#include <cuda_runtime.h>
#include <math.h>

#define Bc   4
#define Sc   8192
#define HID  768
#define Hc   12
#define Dc   64
#define Kc   16
#define NMB  (Sc / Kc)
#define NTOK (Bc * Sc)
#define LN_EPS_F 1e-5f
#define FULL 0xffffffffu

__device__ float g_qk[(size_t)NTOK * HID];
__device__ float g_v[(size_t)NTOK * HID];
__device__ float g_gate[(size_t)NTOK * HID];
__device__ float g_xq[(size_t)NTOK * HID];
__device__ float g_xk[(size_t)NTOK * HID];
__device__ float g_z[(size_t)NTOK * HID];
__device__ float g_zg[(size_t)NTOK * HID];
__device__ float g_lr[(size_t)NTOK * Hc];

// accurate 1/sqrt(var+eps) in double, rounded to float
__device__ __forceinline__ float acc_rstd(float var)
{
    return (float)(1.0 / sqrt((double)var + 1e-5));
}

// ---------------- SGEMM: C[M,N] = A[M,K] * B[K,N], row-major ---------------
#define BM 128
#define BN 128
#define BK 16

__global__ __launch_bounds__(256, 2) void sgemm128(
    const float* __restrict__ A, const float* __restrict__ B,
    float* __restrict__ C, int M, int N, int K)
{
    __shared__ __align__(16) float As[BK][BM + 4];
    __shared__ __align__(16) float Bs[BK][BN];

    const int bx = blockIdx.x, by = blockIdx.y, t = threadIdx.x;
    const int tx = t & 15, ty = t >> 4;
    const float* Ab = A + (size_t)by * BM * K;

    float acc[8][8];
#pragma unroll
    for (int i = 0; i < 8; i++)
#pragma unroll
        for (int j = 0; j < 8; j++) acc[i][j] = 0.0f;

    for (int k0 = 0; k0 < K; k0 += BK) {
#pragma unroll
        for (int i = 0; i < 2; i++) {
            int id = t + i * 256;
            int row = id >> 2;
            int kc4 = (id & 3) * 4;
            float4 a = *(const float4*)(Ab + (size_t)row * K + k0 + kc4);
            As[kc4 + 0][row] = a.x;
            As[kc4 + 1][row] = a.y;
            As[kc4 + 2][row] = a.z;
            As[kc4 + 3][row] = a.w;
        }
#pragma unroll
        for (int i = 0; i < 2; i++) {
            int id = t + i * 256;
            int krow = id >> 5;
            int nc4 = (id & 31) * 4;
            *(float4*)&Bs[krow][nc4] =
                *(const float4*)(B + (size_t)(k0 + krow) * N + bx * BN + nc4);
        }
        __syncthreads();

#pragma unroll
        for (int kk = 0; kk < BK; kk++) {
            float ar[8], br[8];
#pragma unroll
            for (int i = 0; i < 4; i++) { ar[i] = As[kk][ty * 4 + i]; ar[4 + i] = As[kk][ty * 4 + 64 + i]; }
#pragma unroll
            for (int j = 0; j < 4; j++) { br[j] = Bs[kk][tx * 4 + j]; br[4 + j] = Bs[kk][tx * 4 + 64 + j]; }
#pragma unroll
            for (int i = 0; i < 8; i++)
#pragma unroll
                for (int j = 0; j < 8; j++)
                    acc[i][j] = fmaf(ar[i], br[j], acc[i][j]);
        }
        __syncthreads();
    }

    const int mbase = by * BM, nbase = bx * BN;
#pragma unroll
    for (int i = 0; i < 8; i++) {
        int row = mbase + ty * 4 + (i & 3) + (i >> 2) * 64;
#pragma unroll
        for (int j = 0; j < 8; j++) {
            int col = nbase + tx * 4 + (j & 3) + (j >> 2) * 64;
            C[(size_t)row * N + col] = acc[i][j];
        }
    }
}

// ---------------- lr: one warp per head, accurate sigmoid ------------------
__global__ __launch_bounds__(384) void lr_kernel(
    const float* __restrict__ x, const float* __restrict__ lr_w,
    const float* __restrict__ lr_b)
{
    const int token = blockIdx.x;
    const int w = threadIdx.x >> 5;     // head 0..11
    const int lane = threadIdx.x & 31;
    float s = 0.0f;
    for (int e = lane; e < HID; e += 32)
        s += x[(size_t)token * HID + e] * lr_w[w * HID + e];
#pragma unroll
    for (int o = 16; o; o >>= 1) s += __shfl_xor_sync(FULL, s, o);
    if (lane == 0) {
        float z = s + lr_b[w];                       // fp32 rounding like ref
        double sig = 1.0 / (1.0 + exp(-(double)z));  // correctly-rounded sigmoid
        g_lr[(size_t)token * Hc + w] = (float)(sig * (1.0 / 64.0));
    }
}

// ---------------- conv (taps s-4..s-1) + RoPE, accurate sin/cos ------------
__global__ __launch_bounds__(768) void conv_rope_kernel(
    const float* __restrict__ cqw, const float* __restrict__ cqb,
    const float* __restrict__ ckw, const float* __restrict__ ckb)
{
    const int token = blockIdx.x;
    const int s = token & (Sc - 1);
    const int c = threadIdx.x;          // 0..767

    float q = cqb[c];
    float k = ckb[c];
#pragma unroll
    for (int kk = 0; kk < 4; kk++) {
        if (s + kk - 4 >= 0) {
            float xv = g_qk[(size_t)(token + kk - 4) * HID + c];
            q = fmaf(cqw[kk * HID + c], xv, q);
            k = fmaf(ckw[kk * HID + c], xv, k);
        }
    }
    const int d = c & 63;
    const int f = d >> 1;
    // inv_freq = theta^(-2f/64), correctly rounded to fp32
    float invf = (float)pow(10000.0, -(double)(2 * f) * (1.0 / 64.0));
    // angle: single fp32 multiply (matches reference), then exact sin/cos
    float ang = (float)s * invf;
    double sd, cd;
    sincos((double)ang, &sd, &cd);
    float cs = (float)cd, sn = (float)sd;

    float q_p = __shfl_xor_sync(FULL, q, 1);   // pair partner (same warp)
    float k_p = __shfl_xor_sync(FULL, k, 1);

    float oq, ok;
    if ((c & 1) == 0) { oq = q * cs - q_p * sn;  ok = k * cs - k_p * sn; }
    else             { oq = q_p * sn + q * cs;  ok = k_p * sn + k * cs; }
    g_xq[(size_t)token * HID + c] = oq;
    g_xk[(size_t)token * HID + c] = ok;
}

// ---------------- TTT scan: one CTA per (b,h) ------------------------------
#define SD 65

__global__ __launch_bounds__(256) void scan_kernel(
    const float* __restrict__ lti, const float* __restrict__ tns,
    const float* __restrict__ tnb, const float* __restrict__ W1in,
    const float* __restrict__ b1in)
{
    const int bh = blockIdx.x;
    const int b = bh / Hc;
    const int h = bh % Hc;
    const int t = threadIdx.x;
    const int warp = t >> 5;
    const int lane = t & 31;

    __shared__ float W1[Dc * Dc];                 // [c_in][d_out]
    __shared__ float sQ[Kc * SD], sK[Kc * SD], sV[Kc * SD];
    __shared__ float sG[Kc * SD], sZ[Kc * SD];
    __shared__ float sA[Kc][Kc];
    __shared__ float b1[Dc], gsc[Dc], gbi[Dc];
    __shared__ float eta[Kc], tok[Kc], lastE[Kc];

    for (int idx = t; idx < Dc * Dc; idx += 256) W1[idx] = W1in[h * Dc * Dc + idx];
    if (t < Dc) {
        b1[t]  = b1in[h * Dc + t];
        gsc[t] = tns[h * Dc + t];
        gbi[t] = tnb[h * Dc + t];
    }
    if (t < Kc) tok[t] = fmaxf(1.0f / (float)(t + 1) + lti[t], 0.0f);
    __syncthreads();

    for (int m = 0; m < NMB; m++) {
        const int base_tok = b * Sc + m * Kc;

        // load tiles + etas
        for (int idx = t; idx < Kc * Dc; idx += 256) {
            int i = idx >> 6, d = idx & 63;
            size_t g = (size_t)(base_tok + i) * HID + h * Dc + d;
            sQ[i * SD + d] = g_xq[g];
            sK[i * SD + d] = g_xk[g];
            sV[i * SD + d] = g_v[g];
        }
        if (t < Kc) {
            float e = g_lr[(size_t)(base_tok + t) * Hc + h];
            eta[t]   = e;
            lastE[t] = tok[Kc - 1] * e;
        }
        __syncthreads();

        // Z1 = K @ W1 + b1
#pragma unroll
        for (int n = 0; n < 4; n++) {
            int idx = t + n * 256;
            int i = idx >> 6, d = idx & 63;
            float a = b1[d];
#pragma unroll 16
            for (int c = 0; c < Dc; c++)
                a = fmaf(sK[i * SD + c], W1[c * Dc + d], a);
            sZ[i * SD + d] = a;
        }
        __syncthreads();

        // grad = ln_l2_bwd(Z1, V-K)  (warp per row, 2 rows/warp)
#pragma unroll
        for (int rr = 0; rr < 2; rr++) {
            int r = warp + rr * 8;
            float x0 = sZ[r * SD + lane], x1 = sZ[r * SD + lane + 32];
            float su = x0 + x1;
#pragma unroll
            for (int o = 16; o; o >>= 1) su += __shfl_xor_sync(FULL, su, o);
            float mu = su * (1.0f / 64.0f);
            float d0 = x0 - mu, d1 = x1 - mu;
            float vv = d0 * d0 + d1 * d1;
#pragma unroll
            for (int o = 16; o; o >>= 1) vv += __shfl_xor_sync(FULL, vv, o);
            float rstd = acc_rstd(vv * (1.0f / 64.0f));
            float xh0 = d0 * rstd, xh1 = d1 * rstd;
            float g0 = gsc[lane], g1 = gsc[lane + 32];
            float tg0 = sV[r * SD + lane]      - sK[r * SD + lane];
            float tg1 = sV[r * SD + lane + 32] - sK[r * SD + lane + 32];
            float gx0 = (xh0 * g0 + gbi[lane]      - tg0) * g0;
            float gx1 = (xh1 * g1 + gbi[lane + 32] - tg1) * g1;
            float sg = gx0 + gx1;
#pragma unroll
            for (int o = 16; o; o >>= 1) sg += __shfl_xor_sync(FULL, sg, o);
            float mgx = sg * (1.0f / 64.0f);
            float sx = gx0 * xh0 + gx1 * xh1;
#pragma unroll
            for (int o = 16; o; o >>= 1) sx += __shfl_xor_sync(FULL, sx, o);
            float mgxh = sx * (1.0f / 64.0f);
            sG[r * SD + lane]      = (gx0 - mgx - xh0 * mgxh) * rstd;
            sG[r * SD + lane + 32] = (gx1 - mgx - xh1 * mgxh) * rstd;
        }
        __syncthreads();

        // Attn[i][j] = q_i . k_j
        {
            int i = t >> 4, j = t & 15;
            float a = 0.0f;
#pragma unroll 16
            for (int d = 0; d < Dc; d++) a = fmaf(sQ[i * SD + d], sK[j * SD + d], a);
            sA[i][j] = a;
        }
        __syncthreads();

        // Z1_bar = Q@W1 + b1 - sum_{j<=i} tok[i]*eta[j]*(Attn[i][j]+1)*grad[j]
#pragma unroll
        for (int n = 0; n < 4; n++) {
            int idx = t + n * 256;
            int i = idx >> 6, d = idx & 63;
            float a = b1[d];
#pragma unroll 16
            for (int c = 0; c < Dc; c++)
                a = fmaf(sQ[i * SD + c], W1[c * Dc + d], a);
            float ti = tok[i];
            for (int j = 0; j <= i; j++) {
                float coef = ti * eta[j] * (sA[i][j] + 1.0f);
                a -= coef * sG[j * SD + d];
            }
            sZ[i * SD + d] = a;
        }
        __syncthreads();

        // W1 -= (lastE*K)^T @ grad ; b1 -= lastE^T @ grad
#pragma unroll
        for (int n = 0; n < 16; n++) {
            int idx = t + n * 256;
            int c = idx >> 6, d = idx & 63;
            float acc = 0.0f;
#pragma unroll
            for (int j = 0; j < Kc; j++)
                acc = fmaf(lastE[j] * sK[j * SD + c], sG[j * SD + d], acc);
            W1[c * Dc + d] -= acc;
        }
        if (t < Dc) {
            float acc = 0.0f;
#pragma unroll
            for (int j = 0; j < Kc; j++) acc = fmaf(lastE[j], sG[j * SD + t], acc);
            b1[t] -= acc;
        }
        __syncthreads();

        // out = q + ln_fwd(Z1_bar)
#pragma unroll
        for (int rr = 0; rr < 2; rr++) {
            int r = warp + rr * 8;
            float x0 = sZ[r * SD + lane], x1 = sZ[r * SD + lane + 32];
            float su = x0 + x1;
#pragma unroll
            for (int o = 16; o; o >>= 1) su += __shfl_xor_sync(FULL, su, o);
            float mu = su * (1.0f / 64.0f);
            float d0 = x0 - mu, d1 = x1 - mu;
            float vv = d0 * d0 + d1 * d1;
#pragma unroll
            for (int o = 16; o; o >>= 1) vv += __shfl_xor_sync(FULL, vv, o);
            float rstd = acc_rstd(vv * (1.0f / 64.0f));
            size_t gidx = (size_t)(base_tok + r) * HID + h * Dc;
            g_z[gidx + lane]      = sQ[r * SD + lane]      + d0 * rstd * gsc[lane]      + gbi[lane];
            g_z[gidx + lane + 32] = sQ[r * SD + lane + 32] + d1 * rstd * gsc[lane + 32] + gbi[lane + 32];
        }
        __syncthreads();
    }
}

// ---------------- post-LN + GeLU gate --------------------------------------
__device__ __forceinline__ float gelu_tanh(float x)
{
    float x3 = x * x * x;
    return 0.5f * x * (1.0f + tanhf(0.79788456080286536f * (x + 0.044715f * x3)));
}

__global__ __launch_bounds__(256) void ln_gate_kernel(
    const float* __restrict__ ps, const float* __restrict__ pb)
{
    __shared__ float red[8];
    const int token = blockIdx.x;
    const int t = threadIdx.x;
    const int lane = t & 31, w = t >> 5;

    float z[3];
#pragma unroll
    for (int i = 0; i < 3; i++) z[i] = g_z[(size_t)token * HID + t + i * 256];

    float s = z[0] + z[1] + z[2];
#pragma unroll
    for (int o = 16; o; o >>= 1) s += __shfl_xor_sync(FULL, s, o);
    if (lane == 0) red[w] = s;
    __syncthreads();
    float tot = red[0] + red[1] + red[2] + red[3] + red[4] + red[5] + red[6] + red[7];
    float mu = tot * (1.0f / 768.0f);
    __syncthreads();

    float vv = 0.0f;
#pragma unroll
    for (int i = 0; i < 3; i++) { float d = z[i] - mu; vv += d * d; }
#pragma unroll
    for (int o = 16; o; o >>= 1) vv += __shfl_xor_sync(FULL, vv, o);
    if (lane == 0) red[w] = vv;
    __syncthreads();
    float vt = red[0] + red[1] + red[2] + red[3] + red[4] + red[5] + red[6] + red[7];
    float rstd = (float)(1.0 / sqrt((double)(vt * (1.0f / 768.0f)) + 1e-5));

#pragma unroll
    for (int i = 0; i < 3; i++) {
        int c = t + i * 256;
        float zn = (z[i] - mu) * rstd * ps[c] + pb[c];
        float gp = g_gate[(size_t)token * HID + c];
        g_zg[(size_t)token * HID + c] = zn * gelu_tanh(gp);
    }
}

// ---------------- launch ----------------------------------------------------
extern "C" void kernel_launch(void* const* d_in, const int* in_sizes, int n_in,
                              void* d_out, int out_size)
{
    const float *x, *wq, *wv, *wo, *wg, *cqw, *cqb, *ckw, *ckb;
    const float *lrw, *lrb, *lti, *tns, *tnb, *ps, *pb, *W1i, *b1i;

    if (in_sizes[0] == NTOK * HID) {
        // setup_inputs dict order
        x   = (const float*)d_in[0];  wq  = (const float*)d_in[1];
        wv  = (const float*)d_in[2];  wo  = (const float*)d_in[3];
        wg  = (const float*)d_in[4];  cqw = (const float*)d_in[5];
        cqb = (const float*)d_in[6];  ckw = (const float*)d_in[7];
        ckb = (const float*)d_in[8];  lrw = (const float*)d_in[9];
        lrb = (const float*)d_in[10]; lti = (const float*)d_in[11];
        tns = (const float*)d_in[12]; tnb = (const float*)d_in[13];
        ps  = (const float*)d_in[14]; pb  = (const float*)d_in[15];
        W1i = (const float*)d_in[16]; b1i = (const float*)d_in[17];
    } else {
        // ASCII-alphabetical fallback
        W1i = (const float*)d_in[0];  b1i = (const float*)d_in[1];
        ckb = (const float*)d_in[2];  ckw = (const float*)d_in[3];
        cqb = (const float*)d_in[4];  cqw = (const float*)d_in[5];
        lti = (const float*)d_in[6];  lrb = (const float*)d_in[7];
        lrw = (const float*)d_in[8];  pb  = (const float*)d_in[9];
        ps  = (const float*)d_in[10]; tnb = (const float*)d_in[11];
        tns = (const float*)d_in[12]; wg  = (const float*)d_in[13];
        wo  = (const float*)d_in[14]; wq  = (const float*)d_in[15];
        wv  = (const float*)d_in[16]; x   = (const float*)d_in[17];
    }
    float* out = (float*)d_out;

    float *p_qk, *p_v, *p_gate, *p_zg;
    cudaGetSymbolAddress((void**)&p_qk,   g_qk);
    cudaGetSymbolAddress((void**)&p_v,    g_v);
    cudaGetSymbolAddress((void**)&p_gate, g_gate);
    cudaGetSymbolAddress((void**)&p_zg,   g_zg);

    dim3 gg(HID / BN, NTOK / BM);

    sgemm128<<<gg, 256>>>(x, wq, p_qk,   NTOK, HID, HID);
    sgemm128<<<gg, 256>>>(x, wv, p_v,    NTOK, HID, HID);
    sgemm128<<<gg, 256>>>(x, wg, p_gate, NTOK, HID, HID);
    lr_kernel<<<NTOK, 384>>>(x, lrw, lrb);
    conv_rope_kernel<<<NTOK, 768>>>(cqw, cqb, ckw, ckb);
    scan_kernel<<<Bc * Hc, 256>>>(lti, tns, tnb, W1i, b1i);
    ln_gate_kernel<<<NTOK, 256>>>(ps, pb);
    sgemm128<<<gg, 256>>>(p_zg, wo, out, NTOK, HID, HID);
}

// round 11
// speedup vs baseline: 1.7196x; 1.7196x over previous
#include <cuda_runtime.h>
#include <math.h>

#define Bc   4
#define Sc   8192
#define HID  768
#define Hc   12
#define Dc   64
#define Kc   16
#define NMB  (Sc / Kc)
#define NTOK (Bc * Sc)
#define LN_EPS_F 1e-5f
#define FULL 0xffffffffu

__device__ float g_qk[(size_t)NTOK * HID];
__device__ float g_v[(size_t)NTOK * HID];
__device__ float g_gate[(size_t)NTOK * HID];
__device__ float g_xq[(size_t)NTOK * HID];
__device__ float g_xk[(size_t)NTOK * HID];
__device__ float g_z[(size_t)NTOK * HID];
__device__ float g_zg[(size_t)NTOK * HID];
__device__ float g_lr[(size_t)NTOK * Hc];
__device__ float g_rc[(size_t)Sc * 32];   // rope cos table [s][f]
__device__ float g_rs[(size_t)Sc * 32];   // rope sin table [s][f]

// accurate 1/sqrt(var+eps) in double, rounded to float
__device__ __forceinline__ float acc_rstd(float var)
{
    return (float)(1.0 / sqrt((double)var + 1e-5));
}

// ---------------- SGEMM: C[M,N] = A[M,K] * B[K,N], row-major ---------------
#define BM 128
#define BN 128
#define BK 16

__global__ __launch_bounds__(256, 2) void sgemm128(
    const float* __restrict__ A, const float* __restrict__ B,
    float* __restrict__ C, int M, int N, int K)
{
    __shared__ __align__(16) float As[BK][BM + 4];
    __shared__ __align__(16) float Bs[BK][BN];

    const int bx = blockIdx.x, by = blockIdx.y, t = threadIdx.x;
    const int tx = t & 15, ty = t >> 4;
    const float* Ab = A + (size_t)by * BM * K;

    float acc[8][8];
#pragma unroll
    for (int i = 0; i < 8; i++)
#pragma unroll
        for (int j = 0; j < 8; j++) acc[i][j] = 0.0f;

    for (int k0 = 0; k0 < K; k0 += BK) {
#pragma unroll
        for (int i = 0; i < 2; i++) {
            int id = t + i * 256;
            int row = id >> 2;
            int kc4 = (id & 3) * 4;
            float4 a = *(const float4*)(Ab + (size_t)row * K + k0 + kc4);
            As[kc4 + 0][row] = a.x;
            As[kc4 + 1][row] = a.y;
            As[kc4 + 2][row] = a.z;
            As[kc4 + 3][row] = a.w;
        }
#pragma unroll
        for (int i = 0; i < 2; i++) {
            int id = t + i * 256;
            int krow = id >> 5;
            int nc4 = (id & 31) * 4;
            *(float4*)&Bs[krow][nc4] =
                *(const float4*)(B + (size_t)(k0 + krow) * N + bx * BN + nc4);
        }
        __syncthreads();

#pragma unroll
        for (int kk = 0; kk < BK; kk++) {
            float ar[8], br[8];
#pragma unroll
            for (int i = 0; i < 4; i++) { ar[i] = As[kk][ty * 4 + i]; ar[4 + i] = As[kk][ty * 4 + 64 + i]; }
#pragma unroll
            for (int j = 0; j < 4; j++) { br[j] = Bs[kk][tx * 4 + j]; br[4 + j] = Bs[kk][tx * 4 + 64 + j]; }
#pragma unroll
            for (int i = 0; i < 8; i++)
#pragma unroll
                for (int j = 0; j < 8; j++)
                    acc[i][j] = fmaf(ar[i], br[j], acc[i][j]);
        }
        __syncthreads();
    }

    const int mbase = by * BM, nbase = bx * BN;
#pragma unroll
    for (int i = 0; i < 8; i++) {
        int row = mbase + ty * 4 + (i & 3) + (i >> 2) * 64;
#pragma unroll
        for (int j = 0; j < 8; j++) {
            int col = nbase + tx * 4 + (j & 3) + (j >> 2) * 64;
            C[(size_t)row * N + col] = acc[i][j];
        }
    }
}

// ---------------- rope table: accurate double sincos, tiny -----------------
__global__ __launch_bounds__(32) void rope_table_kernel()
{
    const int s = blockIdx.x;
    const int f = threadIdx.x;          // 0..31
    float invf = (float)pow(10000.0, -(double)(2 * f) * (1.0 / 64.0));
    float ang = (float)s * invf;        // fp32 product like reference
    double sd, cd;
    sincos((double)ang, &sd, &cd);
    g_rc[(size_t)s * 32 + f] = (float)cd;
    g_rs[(size_t)s * 32 + f] = (float)sd;
}

// ---------------- lr: one WARP per token, all 12 heads ---------------------
__global__ __launch_bounds__(256) void lr_kernel(
    const float* __restrict__ x, const float* __restrict__ lr_w,
    const float* __restrict__ lr_b)
{
    const int token = blockIdx.x * 8 + (threadIdx.x >> 5);
    const int lane = threadIdx.x & 31;
    const float4* xr = (const float4*)(x + (size_t)token * HID);

    float acc[12];
#pragma unroll
    for (int hh = 0; hh < 12; hh++) acc[hh] = 0.0f;

#pragma unroll
    for (int kk = 0; kk < 6; kk++) {
        float4 xv = xr[lane + 32 * kk];
#pragma unroll
        for (int hh = 0; hh < 12; hh++) {
            float4 wv = *(const float4*)(lr_w + (size_t)hh * HID + (lane + 32 * kk) * 4);
            acc[hh] = fmaf(xv.x, wv.x, acc[hh]);
            acc[hh] = fmaf(xv.y, wv.y, acc[hh]);
            acc[hh] = fmaf(xv.z, wv.z, acc[hh]);
            acc[hh] = fmaf(xv.w, wv.w, acc[hh]);
        }
    }
#pragma unroll
    for (int hh = 0; hh < 12; hh++) {
        float s = acc[hh];
#pragma unroll
        for (int o = 16; o; o >>= 1) s += __shfl_xor_sync(FULL, s, o);
        if (lane == hh) {
            double sig = 1.0 / (1.0 + exp(-(double)(s + lr_b[hh])));
            g_lr[(size_t)token * Hc + hh] = (float)(sig * (1.0 / 64.0));
        }
    }
}

// ---------------- conv (taps s-4..s-1) + RoPE from table -------------------
__global__ __launch_bounds__(768) void conv_rope_kernel(
    const float* __restrict__ cqw, const float* __restrict__ cqb,
    const float* __restrict__ ckw, const float* __restrict__ ckb)
{
    const int token = blockIdx.x;
    const int s = token & (Sc - 1);
    const int c = threadIdx.x;          // 0..767

    float q = cqb[c];
    float k = ckb[c];
#pragma unroll
    for (int kk = 0; kk < 4; kk++) {
        if (s + kk - 4 >= 0) {
            float xv = g_qk[(size_t)(token + kk - 4) * HID + c];
            q = fmaf(cqw[kk * HID + c], xv, q);
            k = fmaf(ckw[kk * HID + c], xv, k);
        }
    }
    const int f = (c & 63) >> 1;
    float cs = g_rc[(size_t)s * 32 + f];
    float sn = g_rs[(size_t)s * 32 + f];

    float q_p = __shfl_xor_sync(FULL, q, 1);
    float k_p = __shfl_xor_sync(FULL, k, 1);

    float oq, ok;
    if ((c & 1) == 0) { oq = q * cs - q_p * sn;  ok = k * cs - k_p * sn; }
    else             { oq = q_p * sn + q * cs;  ok = k_p * sn + k * cs; }
    g_xq[(size_t)token * HID + c] = oq;
    g_xk[(size_t)token * HID + c] = ok;
}

// ---------------- TTT scan: one CTA per (b,h), register-tiled float4 -------
#define SD2 68   // padded row stride; 68*4B = 272B, 16B-aligned rows

__global__ __launch_bounds__(256) void scan_kernel(
    const float* __restrict__ lti, const float* __restrict__ tns,
    const float* __restrict__ tnb, const float* __restrict__ W1in,
    const float* __restrict__ b1in)
{
    const int bh = blockIdx.x;
    const int b = bh / Hc;
    const int h = bh % Hc;
    const int t = threadIdx.x;
    const int warp = t >> 5;
    const int lane = t & 31;

    __shared__ __align__(16) float W1[Dc * Dc];       // [c_in][d_out]
    __shared__ __align__(16) float sQ[Kc * SD2], sK[Kc * SD2], sV[Kc * SD2];
    __shared__ __align__(16) float sG[Kc * SD2], sZ[Kc * SD2];
    __shared__ float sA[Kc][17];
    __shared__ __align__(16) float b1[Dc], gsc[Dc], gbi[Dc];
    __shared__ float eta[Kc], lastE[Kc], tokS[Kc];

    for (int idx = t; idx < Dc * Dc; idx += 256) W1[idx] = W1in[h * Dc * Dc + idx];
    if (t < Dc) {
        b1[t]  = b1in[h * Dc + t];
        gsc[t] = tns[h * Dc + t];
        gbi[t] = tnb[h * Dc + t];
    }
    if (t < Kc) tokS[t] = fmaxf(1.0f / (float)(t + 1) + lti[t], 0.0f);
    __syncthreads();
    const float tok15 = tokS[Kc - 1];

    // per-thread tile-load slot: row = t>>4, columns c4..c4+3
    const int lrow = t >> 4;
    const int lc4  = (t & 15) * 4;

    // prefetch m = 0
    float4 pq, pk, pv;
    float pe = 0.0f;
    {
        size_t g = (size_t)(b * Sc + lrow) * HID + h * Dc + lc4;
        pq = *(const float4*)&g_xq[g];
        pk = *(const float4*)&g_xk[g];
        pv = *(const float4*)&g_v[g];
        if (t < Kc) pe = g_lr[(size_t)(b * Sc + t) * Hc + h];
    }

    for (int m = 0; m < NMB; m++) {
        const int base_tok = b * Sc + m * Kc;

        __syncthreads();   // previous iteration's phases fully done
        *(float4*)&sQ[lrow * SD2 + lc4] = pq;
        *(float4*)&sK[lrow * SD2 + lc4] = pk;
        *(float4*)&sV[lrow * SD2 + lc4] = pv;
        if (t < Kc) { eta[t] = pe; lastE[t] = tok15 * pe; }
        __syncthreads();

        // prefetch next tile (latency hidden behind the phases)
        if (m + 1 < NMB) {
            size_t g = (size_t)(base_tok + Kc + lrow) * HID + h * Dc + lc4;
            pq = *(const float4*)&g_xq[g];
            pk = *(const float4*)&g_xk[g];
            pv = *(const float4*)&g_v[g];
            if (t < Kc) pe = g_lr[(size_t)(base_tok + Kc + t) * Hc + h];
        }

        // ---- P2: Z1 = K @ W1 + b1  (thread -> (i, 4 d's); same fmaf chain)
        {
            const int i = t >> 4, d0 = (t & 15) * 4;
            float4 acc = *(const float4*)&b1[d0];
#pragma unroll
            for (int c = 0; c < Dc; c += 4) {
                float4 kv = *(const float4*)&sK[i * SD2 + c];
                float4 w;
                w = *(const float4*)&W1[(c + 0) * Dc + d0];
                acc.x = fmaf(kv.x, w.x, acc.x); acc.y = fmaf(kv.x, w.y, acc.y);
                acc.z = fmaf(kv.x, w.z, acc.z); acc.w = fmaf(kv.x, w.w, acc.w);
                w = *(const float4*)&W1[(c + 1) * Dc + d0];
                acc.x = fmaf(kv.y, w.x, acc.x); acc.y = fmaf(kv.y, w.y, acc.y);
                acc.z = fmaf(kv.y, w.z, acc.z); acc.w = fmaf(kv.y, w.w, acc.w);
                w = *(const float4*)&W1[(c + 2) * Dc + d0];
                acc.x = fmaf(kv.z, w.x, acc.x); acc.y = fmaf(kv.z, w.y, acc.y);
                acc.z = fmaf(kv.z, w.z, acc.z); acc.w = fmaf(kv.z, w.w, acc.w);
                w = *(const float4*)&W1[(c + 3) * Dc + d0];
                acc.x = fmaf(kv.w, w.x, acc.x); acc.y = fmaf(kv.w, w.y, acc.y);
                acc.z = fmaf(kv.w, w.z, acc.z); acc.w = fmaf(kv.w, w.w, acc.w);
            }
            *(float4*)&sZ[i * SD2 + d0] = acc;
        }
        __syncthreads();

        // ---- P3: grad = ln_l2_bwd(Z1, V-K)  (identical to passing version)
#pragma unroll
        for (int rr = 0; rr < 2; rr++) {
            int r = warp + rr * 8;
            float x0 = sZ[r * SD2 + lane], x1 = sZ[r * SD2 + lane + 32];
            float su = x0 + x1;
#pragma unroll
            for (int o = 16; o; o >>= 1) su += __shfl_xor_sync(FULL, su, o);
            float mu = su * (1.0f / 64.0f);
            float d0 = x0 - mu, d1 = x1 - mu;
            float vv = d0 * d0 + d1 * d1;
#pragma unroll
            for (int o = 16; o; o >>= 1) vv += __shfl_xor_sync(FULL, vv, o);
            float rstd = acc_rstd(vv * (1.0f / 64.0f));
            float xh0 = d0 * rstd, xh1 = d1 * rstd;
            float g0 = gsc[lane], g1 = gsc[lane + 32];
            float tg0 = sV[r * SD2 + lane]      - sK[r * SD2 + lane];
            float tg1 = sV[r * SD2 + lane + 32] - sK[r * SD2 + lane + 32];
            float gx0 = (xh0 * g0 + gbi[lane]      - tg0) * g0;
            float gx1 = (xh1 * g1 + gbi[lane + 32] - tg1) * g1;
            float sg = gx0 + gx1;
#pragma unroll
            for (int o = 16; o; o >>= 1) sg += __shfl_xor_sync(FULL, sg, o);
            float mgx = sg * (1.0f / 64.0f);
            float sx = gx0 * xh0 + gx1 * xh1;
#pragma unroll
            for (int o = 16; o; o >>= 1) sx += __shfl_xor_sync(FULL, sx, o);
            float mgxh = sx * (1.0f / 64.0f);
            sG[r * SD2 + lane]      = (gx0 - mgx - xh0 * mgxh) * rstd;
            sG[r * SD2 + lane + 32] = (gx1 - mgx - xh1 * mgxh) * rstd;
        }

        // ---- P4: Attn[i][j] = q_i . k_j  (independent of P3 -> same phase)
        {
            const int i = t >> 4, j = t & 15;
            float a0 = 0.0f, a1 = 0.0f, a2 = 0.0f, a3 = 0.0f;
#pragma unroll
            for (int c = 0; c < Dc; c += 4) {
                float4 q = *(const float4*)&sQ[i * SD2 + c];
                float4 k = *(const float4*)&sK[j * SD2 + c];
                a0 = fmaf(q.x, k.x, a0); a1 = fmaf(q.y, k.y, a1);
                a2 = fmaf(q.z, k.z, a2); a3 = fmaf(q.w, k.w, a3);
            }
            sA[i][j] = (a0 + a1) + (a2 + a3);
        }
        __syncthreads();

        // ---- P5: Z1_bar = Q@W1 + b1 - sum_{j<=i} tok[i]*eta[j]*(A+1)*grad[j]
        {
            const int i = t >> 4, d0 = (t & 15) * 4;
            float4 acc = *(const float4*)&b1[d0];
#pragma unroll
            for (int c = 0; c < Dc; c += 4) {
                float4 qv = *(const float4*)&sQ[i * SD2 + c];
                float4 w;
                w = *(const float4*)&W1[(c + 0) * Dc + d0];
                acc.x = fmaf(qv.x, w.x, acc.x); acc.y = fmaf(qv.x, w.y, acc.y);
                acc.z = fmaf(qv.x, w.z, acc.z); acc.w = fmaf(qv.x, w.w, acc.w);
                w = *(const float4*)&W1[(c + 1) * Dc + d0];
                acc.x = fmaf(qv.y, w.x, acc.x); acc.y = fmaf(qv.y, w.y, acc.y);
                acc.z = fmaf(qv.y, w.z, acc.z); acc.w = fmaf(qv.y, w.w, acc.w);
                w = *(const float4*)&W1[(c + 2) * Dc + d0];
                acc.x = fmaf(qv.z, w.x, acc.x); acc.y = fmaf(qv.z, w.y, acc.y);
                acc.z = fmaf(qv.z, w.z, acc.z); acc.w = fmaf(qv.z, w.w, acc.w);
                w = *(const float4*)&W1[(c + 3) * Dc + d0];
                acc.x = fmaf(qv.w, w.x, acc.x); acc.y = fmaf(qv.w, w.y, acc.y);
                acc.z = fmaf(qv.w, w.z, acc.z); acc.w = fmaf(qv.w, w.w, acc.w);
            }
            const float ti = tokS[i];
            for (int j = 0; j <= i; j++) {
                float coef = ti * eta[j] * (sA[i][j] + 1.0f);
                float4 g4 = *(const float4*)&sG[j * SD2 + d0];
                acc.x -= coef * g4.x; acc.y -= coef * g4.y;
                acc.z -= coef * g4.z; acc.w -= coef * g4.w;
            }
            *(float4*)&sZ[i * SD2 + d0] = acc;
        }
        __syncthreads();

        // ---- P6: W1 -= (lastE*K)^T @ grad ; b1 -= lastE^T @ grad
        //      (bit-identical j-ascending chains to the passing version)
        {
            const int c = t >> 2, d0 = (t & 3) * 16;
            float acc[16];
#pragma unroll
            for (int q = 0; q < 16; q++) acc[q] = 0.0f;
#pragma unroll
            for (int j = 0; j < Kc; j++) {
                float lek = lastE[j] * sK[j * SD2 + c];
#pragma unroll
                for (int q = 0; q < 4; q++) {
                    float4 g4 = *(const float4*)&sG[j * SD2 + d0 + q * 4];
                    acc[q * 4 + 0] = fmaf(lek, g4.x, acc[q * 4 + 0]);
                    acc[q * 4 + 1] = fmaf(lek, g4.y, acc[q * 4 + 1]);
                    acc[q * 4 + 2] = fmaf(lek, g4.z, acc[q * 4 + 2]);
                    acc[q * 4 + 3] = fmaf(lek, g4.w, acc[q * 4 + 3]);
                }
            }
#pragma unroll
            for (int q = 0; q < 4; q++) {
                float4 w = *(const float4*)&W1[c * Dc + d0 + q * 4];
                w.x -= acc[q * 4 + 0]; w.y -= acc[q * 4 + 1];
                w.z -= acc[q * 4 + 2]; w.w -= acc[q * 4 + 3];
                *(float4*)&W1[c * Dc + d0 + q * 4] = w;
            }
            if (t < Dc) {
                float a = 0.0f;
#pragma unroll
                for (int j = 0; j < Kc; j++) a = fmaf(lastE[j], sG[j * SD2 + t], a);
                b1[t] -= a;
            }
        }

        // ---- P7: out = q + ln_fwd(Z1_bar)  (identical to passing version)
#pragma unroll
        for (int rr = 0; rr < 2; rr++) {
            int r = warp + rr * 8;
            float x0 = sZ[r * SD2 + lane], x1 = sZ[r * SD2 + lane + 32];
            float su = x0 + x1;
#pragma unroll
            for (int o = 16; o; o >>= 1) su += __shfl_xor_sync(FULL, su, o);
            float mu = su * (1.0f / 64.0f);
            float d0 = x0 - mu, d1 = x1 - mu;
            float vv = d0 * d0 + d1 * d1;
#pragma unroll
            for (int o = 16; o; o >>= 1) vv += __shfl_xor_sync(FULL, vv, o);
            float rstd = acc_rstd(vv * (1.0f / 64.0f));
            size_t gidx = (size_t)(base_tok + r) * HID + h * Dc;
            g_z[gidx + lane]      = sQ[r * SD2 + lane]      + d0 * rstd * gsc[lane]      + gbi[lane];
            g_z[gidx + lane + 32] = sQ[r * SD2 + lane + 32] + d1 * rstd * gsc[lane + 32] + gbi[lane + 32];
        }
        // next-iteration top sync orders P6/P7 before the tile stores
    }
}

// ---------------- post-LN + GeLU gate --------------------------------------
__device__ __forceinline__ float gelu_tanh(float x)
{
    float x3 = x * x * x;
    return 0.5f * x * (1.0f + tanhf(0.79788456080286536f * (x + 0.044715f * x3)));
}

__global__ __launch_bounds__(256) void ln_gate_kernel(
    const float* __restrict__ ps, const float* __restrict__ pb)
{
    __shared__ float red[8];
    const int token = blockIdx.x;
    const int t = threadIdx.x;
    const int lane = t & 31, w = t >> 5;

    float z[3];
#pragma unroll
    for (int i = 0; i < 3; i++) z[i] = g_z[(size_t)token * HID + t + i * 256];

    float s = z[0] + z[1] + z[2];
#pragma unroll
    for (int o = 16; o; o >>= 1) s += __shfl_xor_sync(FULL, s, o);
    if (lane == 0) red[w] = s;
    __syncthreads();
    float tot = red[0] + red[1] + red[2] + red[3] + red[4] + red[5] + red[6] + red[7];
    float mu = tot * (1.0f / 768.0f);
    __syncthreads();

    float vv = 0.0f;
#pragma unroll
    for (int i = 0; i < 3; i++) { float d = z[i] - mu; vv += d * d; }
#pragma unroll
    for (int o = 16; o; o >>= 1) vv += __shfl_xor_sync(FULL, vv, o);
    if (lane == 0) red[w] = vv;
    __syncthreads();
    float vt = red[0] + red[1] + red[2] + red[3] + red[4] + red[5] + red[6] + red[7];
    float rstd = (float)(1.0 / sqrt((double)(vt * (1.0f / 768.0f)) + 1e-5));

#pragma unroll
    for (int i = 0; i < 3; i++) {
        int c = t + i * 256;
        float zn = (z[i] - mu) * rstd * ps[c] + pb[c];
        float gp = g_gate[(size_t)token * HID + c];
        g_zg[(size_t)token * HID + c] = zn * gelu_tanh(gp);
    }
}

// ---------------- launch ----------------------------------------------------
extern "C" void kernel_launch(void* const* d_in, const int* in_sizes, int n_in,
                              void* d_out, int out_size)
{
    const float *x, *wq, *wv, *wo, *wg, *cqw, *cqb, *ckw, *ckb;
    const float *lrw, *lrb, *lti, *tns, *tnb, *ps, *pb, *W1i, *b1i;

    if (in_sizes[0] == NTOK * HID) {
        x   = (const float*)d_in[0];  wq  = (const float*)d_in[1];
        wv  = (const float*)d_in[2];  wo  = (const float*)d_in[3];
        wg  = (const float*)d_in[4];  cqw = (const float*)d_in[5];
        cqb = (const float*)d_in[6];  ckw = (const float*)d_in[7];
        ckb = (const float*)d_in[8];  lrw = (const float*)d_in[9];
        lrb = (const float*)d_in[10]; lti = (const float*)d_in[11];
        tns = (const float*)d_in[12]; tnb = (const float*)d_in[13];
        ps  = (const float*)d_in[14]; pb  = (const float*)d_in[15];
        W1i = (const float*)d_in[16]; b1i = (const float*)d_in[17];
    } else {
        W1i = (const float*)d_in[0];  b1i = (const float*)d_in[1];
        ckb = (const float*)d_in[2];  ckw = (const float*)d_in[3];
        cqb = (const float*)d_in[4];  cqw = (const float*)d_in[5];
        lti = (const float*)d_in[6];  lrb = (const float*)d_in[7];
        lrw = (const float*)d_in[8];  pb  = (const float*)d_in[9];
        ps  = (const float*)d_in[10]; tnb = (const float*)d_in[11];
        tns = (const float*)d_in[12]; wg  = (const float*)d_in[13];
        wo  = (const float*)d_in[14]; wq  = (const float*)d_in[15];
        wv  = (const float*)d_in[16]; x   = (const float*)d_in[17];
    }
    float* out = (float*)d_out;

    float *p_qk, *p_v, *p_gate, *p_zg;
    cudaGetSymbolAddress((void**)&p_qk,   g_qk);
    cudaGetSymbolAddress((void**)&p_v,    g_v);
    cudaGetSymbolAddress((void**)&p_gate, g_gate);
    cudaGetSymbolAddress((void**)&p_zg,   g_zg);

    dim3 gg(HID / BN, NTOK / BM);

    rope_table_kernel<<<Sc, 32>>>();
    sgemm128<<<gg, 256>>>(x, wq, p_qk,   NTOK, HID, HID);
    sgemm128<<<gg, 256>>>(x, wv, p_v,    NTOK, HID, HID);
    sgemm128<<<gg, 256>>>(x, wg, p_gate, NTOK, HID, HID);
    lr_kernel<<<NTOK / 8, 256>>>(x, lrw, lrb);
    conv_rope_kernel<<<NTOK, 768>>>(cqw, cqb, ckw, ckb);
    scan_kernel<<<Bc * Hc, 256>>>(lti, tns, tnb, W1i, b1i);
    ln_gate_kernel<<<NTOK, 256>>>(ps, pb);
    sgemm128<<<gg, 256>>>(p_zg, wo, out, NTOK, HID, HID);
}